// round 1
// baseline (speedup 1.0000x reference)
#include <cuda_runtime.h>

// Problem constants: B=16, N=8192, C=128, H=2, hd=64, G=2
#define NB 16
#define NN 8192
#define NC 128
#define NCHUNK 16          // chunks per (b) in weighted-sum pass
#define CHUNK 512          // rows per chunk (16*512 = 8192)

// Scratch (device globals — no allocation allowed)
__device__ float g_u[2 * 128];                       // folded mem·Wk·scale  [h][cin]
__device__ float g_s[NB * 2 * NN];                   // logits -> softmax probs
__device__ float g_part[NB * 2 * NCHUNK * 128];      // partial weighted sums
__device__ float g_fv[NB * 2 * 128];                 // final vectors [b][half][c]

// ---------------------------------------------------------------------------
// Kernel 1: u[h, g*64+i] = scale * sum_j mem[h, 2j+g] * Wk[g, h*32+j, i]
// ---------------------------------------------------------------------------
__global__ void k_prep_u(const float* __restrict__ Wk, const float* __restrict__ mem) {
    int t = threadIdx.x;            // 256 threads: h = t/128, cin = t%128
    int h = t >> 7;
    int cin = t & 127;
    int g = cin >> 6;
    int i = cin & 63;
    float acc = 0.f;
#pragma unroll
    for (int j = 0; j < 32; ++j) {
        int o = h * 32 + j;
        acc += mem[h * 64 + 2 * j + g] * Wk[(g * 64 + o) * 64 + i];
    }
    g_u[t] = acc * 0.125f;          // scale = hd^-0.5 = 1/8
}

// ---------------------------------------------------------------------------
// Kernel 2: logits. One warp per row of x; two dots (h=0,1) per row.
// grid = (16*8192)/8 blocks of 256 threads (8 warps/block)
// ---------------------------------------------------------------------------
__global__ void k_logits(const float* __restrict__ x) {
    __shared__ float su[256];
    int t = threadIdx.x;
    su[t] = g_u[t];
    __syncthreads();

    int rowid = blockIdx.x * 8 + (t >> 5);
    int lane = t & 31;
    const float4* xr = (const float4*)x + (size_t)rowid * 32;
    float4 v = __ldg(xr + lane);
    float4 u0 = ((const float4*)su)[lane];
    float4 u1 = ((const float4*)su)[32 + lane];
    float p0 = v.x * u0.x + v.y * u0.y + v.z * u0.z + v.w * u0.w;
    float p1 = v.x * u1.x + v.y * u1.y + v.z * u1.z + v.w * u1.w;
#pragma unroll
    for (int off = 16; off > 0; off >>= 1) {
        p0 += __shfl_down_sync(0xffffffffu, p0, off);
        p1 += __shfl_down_sync(0xffffffffu, p1, off);
    }
    if (lane == 0) {
        int b = rowid >> 13;
        int m = rowid & (NN - 1);
        g_s[(b * 2 + 0) * NN + m] = p0;
        g_s[(b * 2 + 1) * NN + m] = p1;
    }
}

// ---------------------------------------------------------------------------
// Kernel 3: softmax in-place over each (b,h) row of 8192. 32 blocks x 256.
// ---------------------------------------------------------------------------
__global__ void k_softmax() {
    __shared__ float sv[NN];         // 32KB row cache
    __shared__ float red[256];
    int t = threadIdx.x;
    int bh = blockIdx.x;
    float* srow = g_s + (size_t)bh * NN;
    float4* sv4 = (float4*)sv;
    const float4* sr4 = (const float4*)srow;

    float mx = -1e30f;
#pragma unroll
    for (int i = 0; i < 8; ++i) {
        float4 v = sr4[t + i * 256];
        sv4[t + i * 256] = v;
        mx = fmaxf(mx, fmaxf(fmaxf(v.x, v.y), fmaxf(v.z, v.w)));
    }
    red[t] = mx;
    __syncthreads();
    for (int s = 128; s > 0; s >>= 1) {
        if (t < s) red[t] = fmaxf(red[t], red[t + s]);
        __syncthreads();
    }
    mx = red[0];
    __syncthreads();

    float sum = 0.f;
#pragma unroll
    for (int i = 0; i < 8; ++i) {
        float4 v = sv4[t + i * 256];
        v.x = __expf(v.x - mx); v.y = __expf(v.y - mx);
        v.z = __expf(v.z - mx); v.w = __expf(v.w - mx);
        sv4[t + i * 256] = v;
        sum += v.x + v.y + v.z + v.w;
    }
    red[t] = sum;
    __syncthreads();
    for (int s = 128; s > 0; s >>= 1) {
        if (t < s) red[t] += red[t + s];
        __syncthreads();
    }
    float inv = 1.f / red[0];
#pragma unroll
    for (int i = 0; i < 8; ++i) {
        float4 v = sv4[t + i * 256];
        v.x *= inv; v.y *= inv; v.z *= inv; v.w *= inv;
        ((float4*)srow)[t + i * 256] = v;
    }
}

// ---------------------------------------------------------------------------
// Kernel 4: partial weighted sums  xa_part[b,h,chunk,c] = sum_{m in chunk} a*x
// grid = 16*16 blocks x 256 threads. Deterministic (no atomics).
// Thread layout: mo = t/64 (4 m-lanes), h = (t/32)&1, c4 = t&31 (float4 chan)
// ---------------------------------------------------------------------------
__global__ void k_wsum(const float* __restrict__ x) {
    int t = threadIdx.x;
    int b = blockIdx.x >> 4;
    int chunk = blockIdx.x & (NCHUNK - 1);
    int mo = t >> 6;
    int slot = t & 63;
    int h = slot >> 5;
    int c4 = slot & 31;

    const float* arow = g_s + (size_t)(b * 2 + h) * NN + chunk * CHUNK;
    const float4* xb = (const float4*)x + ((size_t)b * NN + chunk * CHUNK) * 32 + c4;

    float4 acc = make_float4(0.f, 0.f, 0.f, 0.f);
#pragma unroll 4
    for (int m = mo; m < CHUNK; m += 4) {
        float a = __ldg(arow + m);
        float4 v = __ldg(xb + (size_t)m * 32);
        acc.x += a * v.x; acc.y += a * v.y; acc.z += a * v.z; acc.w += a * v.w;
    }

    __shared__ float4 red[256];
    red[t] = acc;
    __syncthreads();
    if (mo == 0) {
        float4 r0 = red[slot], r1 = red[64 + slot], r2 = red[128 + slot], r3 = red[192 + slot];
        float4 r;
        r.x = r0.x + r1.x + r2.x + r3.x;
        r.y = r0.y + r1.y + r2.y + r3.y;
        r.z = r0.z + r1.z + r2.z + r3.z;
        r.w = r0.w + r1.w + r2.w + r3.w;
        float* dst = g_part + (((size_t)(b * 2 + h) * NCHUNK + chunk) * 128) + c4 * 4;
        dst[0] = r.x; dst[1] = r.y; dst[2] = r.z; dst[3] = r.w;
    }
}

// ---------------------------------------------------------------------------
// Kernel 5: finalize. Per b: reduce partials -> xa, row = xa·Wv (interleaved
// map), fv[b,half,c2] = row[half,:]·Wp[c2%2, c2/2, :] + bp. 16 blocks x 128.
// ---------------------------------------------------------------------------
__global__ void k_final(const float* __restrict__ Wv, const float* __restrict__ Wp,
                        const float* __restrict__ bp) {
    int b = blockIdx.x;
    int t = threadIdx.x;   // 128
    __shared__ float xs[256];    // xa[h][c]
    __shared__ float row[128];   // row[h*64+d]

    float a0 = 0.f, a1 = 0.f;
#pragma unroll
    for (int ch = 0; ch < NCHUNK; ++ch) {
        a0 += g_part[((size_t)(b * 2 + 0) * NCHUNK + ch) * 128 + t];
        a1 += g_part[((size_t)(b * 2 + 1) * NCHUNK + ch) * 128 + t];
    }
    xs[t] = a0;
    xs[128 + t] = a1;
    __syncthreads();

    {   // row[b,h,d] = sum_i xa[b,h,g*64+i] * Wv[g, h*32+d/2, i], g=d%2
        int h = t >> 6, d = t & 63;
        int g = d & 1;
        int o = h * 32 + (d >> 1);
        const float* w = Wv + (g * 64 + o) * 64;
        const float* xv = xs + h * 128 + g * 64;
        float acc = 0.f;
#pragma unroll
        for (int i = 0; i < 64; ++i) acc += xv[i] * w[i];
        row[t] = acc;
    }
    __syncthreads();

    {   // fv[b,half,c2] = bp[g2,o2] + sum_i row[half,i]*Wp[g2,o2,i]
        int c2 = t, g2 = c2 & 1, o2 = c2 >> 1;
        const float* w = Wp + (g2 * 64 + o2) * 64;
        float bias = bp[g2 * 64 + o2];
        float f0 = bias, f1 = bias;
#pragma unroll
        for (int i = 0; i < 64; ++i) {
            f0 += row[i] * w[i];
            f1 += row[64 + i] * w[i];
        }
        g_fv[(size_t)b * 256 + c2] = f0;          // half 0  (n < 4096)
        g_fv[(size_t)b * 256 + 128 + c2] = f1;    // half 1  (n >= 4096)
    }
}

// ---------------------------------------------------------------------------
// Kernel 6: broadcast fv over N. out[b,n,c] = fv[b, n>=4096, c]. 64MB stores.
// ---------------------------------------------------------------------------
__global__ void k_bcast(float4* __restrict__ out) {
    int idx = blockIdx.x * 256 + threadIdx.x;   // 4,194,304 float4 total
    int b = idx >> 18;                          // 8192*32 float4 per b
    int rem = idx & 262143;
    int n = rem >> 5;
    int c4 = rem & 31;
    int half = n >> 12;                          // n >= 4096 ?
    float4 v = __ldg((const float4*)g_fv + (size_t)(b * 2 + half) * 32 + c4);
    out[idx] = v;
}

// ---------------------------------------------------------------------------
extern "C" void kernel_launch(void* const* d_in, const int* in_sizes, int n_in,
                              void* d_out, int out_size) {
    const float* x   = (const float*)d_in[0];
    const float* Wk  = (const float*)d_in[1];
    const float* Wv  = (const float*)d_in[2];
    const float* Wp  = (const float*)d_in[3];
    const float* bp  = (const float*)d_in[4];
    const float* mem = (const float*)d_in[5];
    float* out = (float*)d_out;

    k_prep_u<<<1, 256>>>(Wk, mem);
    k_logits<<<(NB * NN) / 8, 256>>>(x);
    k_softmax<<<NB * 2, 256>>>();
    k_wsum<<<NB * NCHUNK, 256>>>(x);
    k_final<<<NB, 128>>>(Wv, Wp, bp);
    k_bcast<<<(NB * NN * NC) / (4 * 256), 256>>>((float4*)out);
}

// round 2
// speedup vs baseline: 1.6250x; 1.6250x over previous
#include <cuda_runtime.h>

// Problem constants: B=16, N=8192, C=128, H=2, hd=64, G=2
#define NB 16
#define NN 8192
#define NC 128
#define NCH 64            // chunks per b in fused pass
#define RPB 128           // rows per block (64 * 128 = 8192)

// Scratch (device globals — no allocation allowed)
__device__ float g_u[2 * 128];                  // folded mem·Wk·scale  [h][cin]
__device__ float g_num[NB * 2 * NCH * 128];     // per-chunk Σ e·x   (1 MB)
__device__ float g_den[NB * 2 * NCH];           // per-chunk Σ e
__device__ float g_fv[NB * 2 * 128];            // final vectors [b][half][c]

// ---------------------------------------------------------------------------
// Kernel 1: u[h, g*64+i] = scale * sum_j mem[h, 2j+g] * Wk[g, h*32+j, i]
// ---------------------------------------------------------------------------
__global__ void k_prep_u(const float* __restrict__ Wk, const float* __restrict__ mem) {
    int t = threadIdx.x;            // 256 threads: h = t/128, cin = t%128
    int h = t >> 7;
    int cin = t & 127;
    int g = cin >> 6;
    int i = cin & 63;
    float acc = 0.f;
#pragma unroll
    for (int j = 0; j < 32; ++j) {
        int o = h * 32 + j;
        acc += mem[h * 64 + 2 * j + g] * Wk[(g * 64 + o) * 64 + i];
    }
    g_u[t] = acc * 0.125f;          // scale = hd^-0.5 = 1/8
}

// ---------------------------------------------------------------------------
// Kernel 2 (FUSED): logits + exp (no max shift; logits are O(1)) + weighted
// accumulation, single pass over x. One warp streams 16 contiguous rows.
// grid = NB*NCH = 1024 blocks x 256 threads (8 warps).
// Writes per-chunk partials (deterministic; no atomics).
// ---------------------------------------------------------------------------
__global__ void k_fused(const float* __restrict__ x) {
    __shared__ float su[256];
    __shared__ float4 s0[8][32];
    __shared__ float4 s1[8][32];
    __shared__ float sden[8][2];
    int t = threadIdx.x;
    su[t] = g_u[t];
    __syncthreads();

    int b = blockIdx.x >> 6;
    int chunk = blockIdx.x & (NCH - 1);
    int w = t >> 5, lane = t & 31;
    float4 u0 = ((const float4*)su)[lane];
    float4 u1 = ((const float4*)su)[32 + lane];

    const float4* xb = (const float4*)x
        + ((size_t)b * NN + (size_t)chunk * RPB + (size_t)w * 16) * 32 + lane;

    float4 acc0 = make_float4(0.f, 0.f, 0.f, 0.f);
    float4 acc1 = make_float4(0.f, 0.f, 0.f, 0.f);
    float den0 = 0.f, den1 = 0.f;

#pragma unroll 4
    for (int r = 0; r < 16; ++r) {
        float4 v = __ldg(xb + (size_t)r * 32);
        float p0 = v.x * u0.x + v.y * u0.y + v.z * u0.z + v.w * u0.w;
        float p1 = v.x * u1.x + v.y * u1.y + v.z * u1.z + v.w * u1.w;
#pragma unroll
        for (int off = 16; off > 0; off >>= 1) {
            p0 += __shfl_xor_sync(0xffffffffu, p0, off);
            p1 += __shfl_xor_sync(0xffffffffu, p1, off);
        }
        float e0 = __expf(p0);
        float e1 = __expf(p1);
        acc0.x += e0 * v.x; acc0.y += e0 * v.y; acc0.z += e0 * v.z; acc0.w += e0 * v.w;
        acc1.x += e1 * v.x; acc1.y += e1 * v.y; acc1.z += e1 * v.z; acc1.w += e1 * v.w;
        den0 += e0; den1 += e1;
    }

    s0[w][lane] = acc0;
    s1[w][lane] = acc1;
    if (lane == 0) { sden[w][0] = den0; sden[w][1] = den1; }
    __syncthreads();

    if (t < 32) {                       // reduce num (h=0), 32 float4 channels
        float4 r = s0[0][t];
#pragma unroll
        for (int ww = 1; ww < 8; ++ww) {
            float4 q = s0[ww][t];
            r.x += q.x; r.y += q.y; r.z += q.z; r.w += q.w;
        }
        ((float4*)g_num)[((size_t)(b * 2 + 0) * NCH + chunk) * 32 + t] = r;
    } else if (t < 64) {                // reduce num (h=1)
        int c = t - 32;
        float4 r = s1[0][c];
#pragma unroll
        for (int ww = 1; ww < 8; ++ww) {
            float4 q = s1[ww][c];
            r.x += q.x; r.y += q.y; r.z += q.z; r.w += q.w;
        }
        ((float4*)g_num)[((size_t)(b * 2 + 1) * NCH + chunk) * 32 + c] = r;
    } else if (t < 66) {                // reduce den
        int h = t - 64;
        float d = 0.f;
#pragma unroll
        for (int ww = 0; ww < 8; ++ww) d += sden[ww][h];
        g_den[(size_t)(b * 2 + h) * NCH + chunk] = d;
    }
}

// ---------------------------------------------------------------------------
// Kernel 3: finalize. Per b: reduce chunk partials -> xa = num/den,
// row = xa·Wv (interleaved map), fv = row·Wp + bp. 16 blocks x 128 threads.
// ---------------------------------------------------------------------------
__global__ void k_final(const float* __restrict__ Wv, const float* __restrict__ Wp,
                        const float* __restrict__ bp) {
    int b = blockIdx.x;
    int t = threadIdx.x;   // 128
    __shared__ float xs[256];    // xa[h][c]
    __shared__ float row[128];   // row[h*64+d]

    float a0 = 0.f, a1 = 0.f;
#pragma unroll
    for (int ch = 0; ch < NCH; ++ch) {
        a0 += g_num[((size_t)(b * 2 + 0) * NCH + ch) * 128 + t];
        a1 += g_num[((size_t)(b * 2 + 1) * NCH + ch) * 128 + t];
    }
    float d0 = 0.f, d1 = 0.f;
#pragma unroll
    for (int ch = 0; ch < NCH; ++ch) {
        d0 += g_den[(size_t)(b * 2 + 0) * NCH + ch];
        d1 += g_den[(size_t)(b * 2 + 1) * NCH + ch];
    }
    xs[t] = a0 / d0;
    xs[128 + t] = a1 / d1;
    __syncthreads();

    {   // row[b,h,d] = sum_i xa[b,h,g*64+i] * Wv[g, h*32+d/2, i], g=d%2
        int h = t >> 6, d = t & 63;
        int g = d & 1;
        int o = h * 32 + (d >> 1);
        const float* w = Wv + (g * 64 + o) * 64;
        const float* xv = xs + h * 128 + g * 64;
        float acc = 0.f;
#pragma unroll
        for (int i = 0; i < 64; ++i) acc += xv[i] * w[i];
        row[t] = acc;
    }
    __syncthreads();

    {   // fv[b,half,c2] = bp[g2,o2] + sum_i row[half,i]*Wp[g2,o2,i]
        int c2 = t, g2 = c2 & 1, o2 = c2 >> 1;
        const float* w = Wp + (g2 * 64 + o2) * 64;
        float bias = bp[g2 * 64 + o2];
        float f0 = bias, f1 = bias;
#pragma unroll
        for (int i = 0; i < 64; ++i) {
            f0 += row[i] * w[i];
            f1 += row[64 + i] * w[i];
        }
        g_fv[(size_t)b * 256 + c2] = f0;          // half 0  (n < 4096)
        g_fv[(size_t)b * 256 + 128 + c2] = f1;    // half 1  (n >= 4096)
    }
}

// ---------------------------------------------------------------------------
// Kernel 4: broadcast fv over N. out[b,n,c] = fv[b, n>=4096, c]. 64MB stores.
// ---------------------------------------------------------------------------
__global__ void k_bcast(float4* __restrict__ out) {
    int idx = blockIdx.x * 256 + threadIdx.x;   // 4,194,304 float4 total
    int b = idx >> 18;                          // 8192*32 float4 per b
    int rem = idx & 262143;
    int n = rem >> 5;
    int c4 = rem & 31;
    int half = n >> 12;                          // n >= 4096 ?
    float4 v = __ldg((const float4*)g_fv + (size_t)(b * 2 + half) * 32 + c4);
    out[idx] = v;
}

// ---------------------------------------------------------------------------
extern "C" void kernel_launch(void* const* d_in, const int* in_sizes, int n_in,
                              void* d_out, int out_size) {
    const float* x   = (const float*)d_in[0];
    const float* Wk  = (const float*)d_in[1];
    const float* Wv  = (const float*)d_in[2];
    const float* Wp  = (const float*)d_in[3];
    const float* bp  = (const float*)d_in[4];
    const float* mem = (const float*)d_in[5];
    float* out = (float*)d_out;

    k_prep_u<<<1, 256>>>(Wk, mem);
    k_fused<<<NB * NCH, 256>>>(x);
    k_final<<<NB, 128>>>(Wv, Wp, bp);
    k_bcast<<<(NB * NN * NC) / (4 * 256), 256>>>((float4*)out);
}